// round 8
// baseline (speedup 1.0000x reference)
#include <cuda_runtime.h>
#include <math.h>
#include <stdint.h>

// Problem constants (fixed by the reference)
#define S_LEN   2048
#define BATCH   2
#define DMODEL  1024
#define NHEAD   16
#define DHEAD   64
#define MROWS   (S_LEN * BATCH)

// Scratch (no allocation allowed)
__device__ float g_q[S_LEN * BATCH * DMODEL];
__device__ float g_k[S_LEN * BATCH * DMODEL];
__device__ float g_v[S_LEN * BATCH * DMODEL];
__device__ float g_attn[S_LEN * BATCH * DMODEL];
// tf32-rounded weights
__device__ float g_wq[DMODEL * DMODEL];
__device__ float g_wk[DMODEL * DMODEL];
__device__ float g_wv[DMODEL * DMODEL];
__device__ float g_wo[DMODEL * DMODEL];

// ---------------------------------------------------------------------------
// Helpers
// ---------------------------------------------------------------------------
__device__ __forceinline__ float tf32_rna(float x) {
    uint32_t r;
    asm("cvt.rna.tf32.f32 %0, %1;" : "=r"(r) : "f"(x));
    return __uint_as_float(r);
}

__device__ __forceinline__ void mma8(float c[4], const uint32_t a[4],
                                     const uint32_t b[2]) {
    asm volatile(
        "mma.sync.aligned.m16n8k8.row.col.f32.tf32.tf32.f32 "
        "{%0,%1,%2,%3}, {%4,%5,%6,%7}, {%8,%9}, {%0,%1,%2,%3};\n"
        : "+f"(c[0]), "+f"(c[1]), "+f"(c[2]), "+f"(c[3])
        : "r"(a[0]), "r"(a[1]), "r"(a[2]), "r"(a[3]),
          "r"(b[0]), "r"(b[1]));
}

__device__ __forceinline__ void cp_async16(uint32_t smem_addr, const void* gptr) {
    asm volatile("cp.async.cg.shared.global [%0], [%1], 16;\n"
                 :: "r"(smem_addr), "l"(gptr));
}
__device__ __forceinline__ void cp_commit() {
    asm volatile("cp.async.commit_group;\n");
}
__device__ __forceinline__ void cp_wait1() {
    asm volatile("cp.async.wait_group 1;\n");
}
__device__ __forceinline__ uint32_t smem_u32(const void* p) {
    return (uint32_t)__cvta_generic_to_shared(p);
}

__device__ __forceinline__ void split2(float x, uint32_t& hi, uint32_t& lo) {
    float h = tf32_rna(x);
    hi = __float_as_uint(h);
    lo = __float_as_uint(x - h);
}

// ---------------------------------------------------------------------------
// Weight pre-rounding, all four matrices in one launch (grid.z selects).
// ---------------------------------------------------------------------------
struct RoundArgs { const float* w[4]; float* o[4]; };

__global__ void __launch_bounds__(256)
round_w_kernel(RoundArgs a)
{
    const int z = blockIdx.z;
    const int i = (blockIdx.x * 256 + threadIdx.x) * 4;
    float4 v = *(const float4*)(a.w[z] + i);
    v.x = tf32_rna(v.x); v.y = tf32_rna(v.y);
    v.z = tf32_rna(v.z); v.w = tf32_rna(v.w);
    *(float4*)(a.o[z] + i) = v;
}

// ---------------------------------------------------------------------------
// Projection GEMM core: Y[m,n] = sum_k X[m,k]*Whi[n,k] + bias[n]
// Whi pre-rounded tf32 -> raw B frags; X split in regs -> 2-pass.
// 128x128 tile, BK=32, 256 thr, cp.async double buffer.
// ---------------------------------------------------------------------------
#define GPAD 36
#define G_TILE_FLOATS (128 * GPAD)
#define G_SMEM_FLOATS (4 * G_TILE_FLOATS)
#define G_SMEM_BYTES  (G_SMEM_FLOATS * 4)   // 73728

__device__ __forceinline__ void gemm_body(
    const float* __restrict__ X, const float* __restrict__ W,
    const float* __restrict__ bias, float* __restrict__ Y,
    int M, int N, int K, bool round_out, float* sm)
{
    float* As = sm;
    float* Bs = sm + 2 * G_TILE_FLOATS;

    const int tid  = threadIdx.x;
    const int lane = tid & 31;
    const int w    = tid >> 5;
    const int wm   = w >> 2;
    const int wn   = w & 3;
    const int m0   = blockIdx.y * 128;
    const int n0   = blockIdx.x * 128;
    const int g    = lane >> 2;
    const int tg   = lane & 3;

    float c[4][4][4] = {};
    const uint32_t sbase = smem_u32(sm);

    auto issue_tile = [&](int k0, int buf) {
        #pragma unroll
        for (int i = 0; i < 4; i++) {
            const int ch  = i * 256 + tid;
            const int row = ch >> 3;
            const int seg = ch & 7;
            const uint32_t soff = (uint32_t)(row * GPAD + seg * 4) * 4u;
            cp_async16(sbase + (uint32_t)(buf * G_TILE_FLOATS * 4) + soff,
                       X + (size_t)(m0 + row) * K + k0 + seg * 4);
            cp_async16(sbase + (uint32_t)((2 + buf) * G_TILE_FLOATS * 4) + soff,
                       W + (size_t)(n0 + row) * K + k0 + seg * 4);
        }
    };

    issue_tile(0, 0);
    cp_commit();

    const int NT = K / 32;
    for (int kt = 0; kt < NT; kt++) {
        if (kt + 1 < NT) issue_tile((kt + 1) * 32, (kt + 1) & 1);
        cp_commit();
        cp_wait1();
        __syncthreads();

        const float* At = As + (kt & 1) * G_TILE_FLOATS;
        const float* Bt = Bs + (kt & 1) * G_TILE_FLOATS;

        #pragma unroll
        for (int ks = 0; ks < 4; ks++) {
            const int kk = ks * 8;
            uint32_t ahi[4][4], alo[4][4];
            #pragma unroll
            for (int mt = 0; mt < 4; mt++) {
                const int r = (wm * 64 + mt * 16 + g) * GPAD + kk;
                split2(At[r + tg],                ahi[mt][0], alo[mt][0]);
                split2(At[r + 8 * GPAD + tg],     ahi[mt][1], alo[mt][1]);
                split2(At[r + tg + 4],            ahi[mt][2], alo[mt][2]);
                split2(At[r + 8 * GPAD + tg + 4], ahi[mt][3], alo[mt][3]);
            }
            uint32_t bh[4][2];
            #pragma unroll
            for (int nt = 0; nt < 4; nt++) {
                const int r = (wn * 32 + nt * 8 + g) * GPAD + kk;
                bh[nt][0] = __float_as_uint(Bt[r + tg]);
                bh[nt][1] = __float_as_uint(Bt[r + tg + 4]);
            }
            #pragma unroll
            for (int mt = 0; mt < 4; mt++)
                #pragma unroll
                for (int nt = 0; nt < 4; nt++) {
                    mma8(c[mt][nt], ahi[mt], bh[nt]);
                    mma8(c[mt][nt], alo[mt], bh[nt]);
                }
        }
        __syncthreads();
    }

    #pragma unroll
    for (int mt = 0; mt < 4; mt++) {
        const int r0 = m0 + wm * 64 + mt * 16 + g;
        #pragma unroll
        for (int nt = 0; nt < 4; nt++) {
            const int cb = n0 + wn * 32 + nt * 8 + tg * 2;
            float2 bv = *(const float2*)(bias + cb);
            float2 v0, v1;
            v0.x = c[mt][nt][0] + bv.x; v0.y = c[mt][nt][1] + bv.y;
            v1.x = c[mt][nt][2] + bv.x; v1.y = c[mt][nt][3] + bv.y;
            if (round_out) {
                v0.x = tf32_rna(v0.x); v0.y = tf32_rna(v0.y);
                v1.x = tf32_rna(v1.x); v1.y = tf32_rna(v1.y);
            }
            *(float2*)(Y + (size_t)r0 * N + cb)       = v0;
            *(float2*)(Y + (size_t)(r0 + 8) * N + cb) = v1;
        }
    }
}

// Merged Q/K/V projection: blockIdx.z selects the stream.
struct QKVArgs {
    const float* X[3];
    const float* W[3];
    const float* bias[3];
    float* Y[3];
};

__global__ void __launch_bounds__(256)
gemm_qkv_kernel(QKVArgs a)
{
    extern __shared__ float sm[];
    const int z = blockIdx.z;
    // z=0 -> Q (no rounding), z=1,2 -> K,V (round outputs to tf32)
    gemm_body(a.X[z], a.W[z], a.bias[z], a.Y[z],
              MROWS, DMODEL, DMODEL, z > 0, sm);
}

__global__ void __launch_bounds__(256)
gemm_o_kernel(const float* __restrict__ X, const float* __restrict__ W,
              const float* __restrict__ bias, float* __restrict__ Y)
{
    extern __shared__ float sm[];
    gemm_body(X, W, bias, Y, MROWS, DMODEL, DMODEL, false, sm);
}

// ---------------------------------------------------------------------------
// Tensor-core flash attention — EXACT R5 numerics (the proven-passing path):
// scaled scores, __expf, scaled-domain running max, unconditional rescale,
// P stored raw + split at read -> 2-pass PV. K/V pre-rounded tf32.
// ---------------------------------------------------------------------------
#define AT_PAD 68
#define KV_TILE_FLOATS (64 * AT_PAD)
#define AT_KS(buf) ((buf) * KV_TILE_FLOATS)
#define AT_VS(buf) ((2 + (buf)) * KV_TILE_FLOATS)
#define AT_PS      (4 * KV_TILE_FLOATS)
#define AT_SMEM_FLOATS (4 * KV_TILE_FLOATS + 128 * AT_PAD)
#define AT_SMEM_BYTES  (AT_SMEM_FLOATS * 4)

__global__ void __launch_bounds__(256)
attn_tc_kernel(const float* __restrict__ Q, const float* __restrict__ Kp,
               const float* __restrict__ Vp, float* __restrict__ O)
{
    extern __shared__ float sm[];
    const int tid  = threadIdx.x;
    const int lane = tid & 31;
    const int w    = tid >> 5;
    const int g    = lane >> 2;
    const int tg   = lane & 3;

    const int qblk = blockIdx.x;
    const int hb   = blockIdx.y;
    const int h    = hb >> 1;
    const int b    = hb & 1;
    const int hoff = h * DHEAD;

    const uint32_t sbase = smem_u32(sm);

    auto gidx = [&](int row) -> size_t {
        return ((size_t)row * BATCH + b) * DMODEL + hoff;
    };

    // stage Q tile into P buffer, build persistent split fragments
    {
        #pragma unroll
        for (int i = 0; i < 8; i++) {
            const int ch  = i * 256 + tid;
            const int row = ch >> 4;
            const int seg = ch & 15;
            float4 v = *(const float4*)(Q + gidx(qblk * 128 + row) + seg * 4);
            *(float4*)&sm[AT_PS + row * AT_PAD + seg * 4] = v;
        }
    }
    __syncthreads();

    uint32_t qhi[8][4], qlo[8][4];
    {
        const float* Qs = sm + AT_PS + (w * 16) * AT_PAD;
        #pragma unroll
        for (int ks = 0; ks < 8; ks++) {
            const int kk = ks * 8;
            split2(Qs[g * AT_PAD + kk + tg],           qhi[ks][0], qlo[ks][0]);
            split2(Qs[(g + 8) * AT_PAD + kk + tg],     qhi[ks][1], qlo[ks][1]);
            split2(Qs[g * AT_PAD + kk + tg + 4],       qhi[ks][2], qlo[ks][2]);
            split2(Qs[(g + 8) * AT_PAD + kk + tg + 4], qhi[ks][3], qlo[ks][3]);
        }
    }
    __syncthreads();

    auto issue_kv = [&](int kb, int buf) {
        #pragma unroll
        for (int i = 0; i < 4; i++) {
            const int ch  = i * 256 + tid;
            const int row = ch >> 4;
            const int seg = ch & 15;
            const uint32_t soff = (uint32_t)(row * AT_PAD + seg * 4) * 4u;
            const size_t go = gidx(kb + row) + seg * 4;
            cp_async16(sbase + (uint32_t)(AT_KS(buf) * 4) + soff, Kp + go);
            cp_async16(sbase + (uint32_t)(AT_VS(buf) * 4) + soff, Vp + go);
        }
    };

    issue_kv(0, 0);
    cp_commit();

    float o[8][4] = {};
    float mrow0 = -1e30f, mrow1 = -1e30f;  // scaled-score domain (R5)
    float lrow0 = 0.0f,   lrow1 = 0.0f;
    const float scale = 0.125f;

    float* Pw = sm + AT_PS + (w * 16) * AT_PAD;

    const int NKT = S_LEN / 64;
    for (int kt = 0; kt < NKT; kt++) {
        if (kt + 1 < NKT) issue_kv((kt + 1) * 64, (kt + 1) & 1);
        cp_commit();
        cp_wait1();
        __syncthreads();

        const float* Kt = sm + AT_KS(kt & 1);
        const float* Vt = sm + AT_VS(kt & 1);

        // ---- QK^T (raw K fragments; 2-pass on Q split) ----
        float s[8][4] = {};
        #pragma unroll
        for (int ks = 0; ks < 8; ks++) {
            const int kk = ks * 8;
            #pragma unroll
            for (int nt = 0; nt < 8; nt++) {
                const int r = (nt * 8 + g) * AT_PAD + kk;
                uint32_t bh[2];
                bh[0] = __float_as_uint(Kt[r + tg]);
                bh[1] = __float_as_uint(Kt[r + tg + 4]);
                mma8(s[nt], qhi[ks], bh);
                mma8(s[nt], qlo[ks], bh);
            }
        }

        // ---- online softmax (R5: scaled domain, __expf, unconditional) ----
        float mx0 = -1e30f, mx1 = -1e30f;
        #pragma unroll
        for (int nt = 0; nt < 8; nt++) {
            s[nt][0] *= scale; s[nt][1] *= scale;
            s[nt][2] *= scale; s[nt][3] *= scale;
            mx0 = fmaxf(mx0, fmaxf(s[nt][0], s[nt][1]));
            mx1 = fmaxf(mx1, fmaxf(s[nt][2], s[nt][3]));
        }
        mx0 = fmaxf(mx0, __shfl_xor_sync(0xffffffffu, mx0, 1));
        mx0 = fmaxf(mx0, __shfl_xor_sync(0xffffffffu, mx0, 2));
        mx1 = fmaxf(mx1, __shfl_xor_sync(0xffffffffu, mx1, 1));
        mx1 = fmaxf(mx1, __shfl_xor_sync(0xffffffffu, mx1, 2));

        const float mn0 = fmaxf(mrow0, mx0);
        const float mn1 = fmaxf(mrow1, mx1);
        const float corr0 = __expf(mrow0 - mn0);
        const float corr1 = __expf(mrow1 - mn1);
        mrow0 = mn0; mrow1 = mn1;

        float sum0 = 0.0f, sum1 = 0.0f;
        #pragma unroll
        for (int nt = 0; nt < 8; nt++) {
            s[nt][0] = __expf(s[nt][0] - mn0);
            s[nt][1] = __expf(s[nt][1] - mn0);
            s[nt][2] = __expf(s[nt][2] - mn1);
            s[nt][3] = __expf(s[nt][3] - mn1);
            sum0 += s[nt][0] + s[nt][1];
            sum1 += s[nt][2] + s[nt][3];
        }
        sum0 += __shfl_xor_sync(0xffffffffu, sum0, 1);
        sum0 += __shfl_xor_sync(0xffffffffu, sum0, 2);
        sum1 += __shfl_xor_sync(0xffffffffu, sum1, 1);
        sum1 += __shfl_xor_sync(0xffffffffu, sum1, 2);
        lrow0 = lrow0 * corr0 + sum0;
        lrow1 = lrow1 * corr1 + sum1;

        #pragma unroll
        for (int nt = 0; nt < 8; nt++) {
            o[nt][0] *= corr0; o[nt][1] *= corr0;
            o[nt][2] *= corr1; o[nt][3] *= corr1;
        }

        // ---- P -> smem raw (own warp rows) ----
        #pragma unroll
        for (int nt = 0; nt < 8; nt++) {
            float2 p01; p01.x = s[nt][0]; p01.y = s[nt][1];
            float2 p23; p23.x = s[nt][2]; p23.y = s[nt][3];
            *(float2*)&Pw[g * AT_PAD + nt * 8 + 2 * tg]       = p01;
            *(float2*)&Pw[(g + 8) * AT_PAD + nt * 8 + 2 * tg] = p23;
        }
        __syncwarp();

        // ---- P @ V : 2-pass (P split at read; V pre-rounded raw) ----
        #pragma unroll
        for (int ks2 = 0; ks2 < 8; ks2++) {
            const int kk = ks2 * 8;
            uint32_t phi[4], plo[4];
            split2(Pw[g * AT_PAD + kk + tg],           phi[0], plo[0]);
            split2(Pw[(g + 8) * AT_PAD + kk + tg],     phi[1], plo[1]);
            split2(Pw[g * AT_PAD + kk + tg + 4],       phi[2], plo[2]);
            split2(Pw[(g + 8) * AT_PAD + kk + tg + 4], phi[3], plo[3]);
            #pragma unroll
            for (int nt = 0; nt < 8; nt++) {
                uint32_t vh[2];
                vh[0] = __float_as_uint(Vt[(kk + tg) * AT_PAD + nt * 8 + g]);
                vh[1] = __float_as_uint(Vt[(kk + tg + 4) * AT_PAD + nt * 8 + g]);
                mma8(o[nt], phi, vh);
                mma8(o[nt], plo, vh);
            }
        }
        __syncwarp();
    }

    const float inv0 = 1.0f / lrow0;
    const float inv1 = 1.0f / lrow1;
    const int q0 = qblk * 128 + w * 16 + g;
    #pragma unroll
    for (int nt = 0; nt < 8; nt++) {
        float2 v0, v1;
        v0.x = o[nt][0] * inv0; v0.y = o[nt][1] * inv0;
        v1.x = o[nt][2] * inv1; v1.y = o[nt][3] * inv1;
        *(float2*)(O + gidx(q0) + nt * 8 + 2 * tg)     = v0;
        *(float2*)(O + gidx(q0 + 8) + nt * 8 + 2 * tg) = v1;
    }
}

// ---------------------------------------------------------------------------
extern "C" void kernel_launch(void* const* d_in, const int* in_sizes, int n_in,
                              void* d_out, int out_size)
{
    (void)in_sizes; (void)n_in; (void)out_size;
    const float* query = (const float*)d_in[0];
    const float* key   = (const float*)d_in[1];
    const float* value = (const float*)d_in[2];
    const float* Wq    = (const float*)d_in[3];
    const float* bq    = (const float*)d_in[4];
    const float* Wk    = (const float*)d_in[5];
    const float* bk    = (const float*)d_in[6];
    const float* Wv    = (const float*)d_in[7];
    const float* bv    = (const float*)d_in[8];
    const float* Wo    = (const float*)d_in[9];
    const float* bo    = (const float*)d_in[10];
    float* out = (float*)d_out;

    float *qp, *kp, *vp, *ap, *wq, *wk, *wv, *wo;
    cudaGetSymbolAddress((void**)&qp, g_q);
    cudaGetSymbolAddress((void**)&kp, g_k);
    cudaGetSymbolAddress((void**)&vp, g_v);
    cudaGetSymbolAddress((void**)&ap, g_attn);
    cudaGetSymbolAddress((void**)&wq, g_wq);
    cudaGetSymbolAddress((void**)&wk, g_wk);
    cudaGetSymbolAddress((void**)&wv, g_wv);
    cudaGetSymbolAddress((void**)&wo, g_wo);

    cudaFuncSetAttribute(gemm_qkv_kernel,
                         cudaFuncAttributeMaxDynamicSharedMemorySize, G_SMEM_BYTES);
    cudaFuncSetAttribute(gemm_o_kernel,
                         cudaFuncAttributeMaxDynamicSharedMemorySize, G_SMEM_BYTES);
    cudaFuncSetAttribute(attn_tc_kernel,
                         cudaFuncAttributeMaxDynamicSharedMemorySize, AT_SMEM_BYTES);

    // Pre-round all four weight matrices in one launch
    RoundArgs ra;
    ra.w[0] = Wq; ra.w[1] = Wk; ra.w[2] = Wv; ra.w[3] = Wo;
    ra.o[0] = wq; ra.o[1] = wk; ra.o[2] = wv; ra.o[3] = wo;
    {
        dim3 rgrid(DMODEL * DMODEL / (256 * 4), 1, 4);
        round_w_kernel<<<rgrid, 256>>>(ra);
    }

    // Merged Q/K/V projections
    QKVArgs qa;
    qa.X[0] = query; qa.X[1] = key; qa.X[2] = value;
    qa.W[0] = wq;    qa.W[1] = wk;  qa.W[2] = wv;
    qa.bias[0] = bq; qa.bias[1] = bk; qa.bias[2] = bv;
    qa.Y[0] = qp;    qa.Y[1] = kp;  qa.Y[2] = vp;
    {
        dim3 ggrid(DMODEL / 128, MROWS / 128, 3);
        gemm_qkv_kernel<<<ggrid, 256, G_SMEM_BYTES>>>(qa);
    }

    dim3 agrid(S_LEN / 128, NHEAD * BATCH);
    attn_tc_kernel<<<agrid, 256, AT_SMEM_BYTES>>>(qp, kp, vp, ap);

    dim3 ogrid(DMODEL / 128, MROWS / 128);
    gemm_o_kernel<<<ogrid, 256, G_SMEM_BYTES>>>(ap, wo, bo, out);
}